// round 1
// baseline (speedup 1.0000x reference)
#include <cuda_runtime.h>
#include <math.h>

#define BB  2
#define SS  2048
#define EE  1024
#define HH  16
#define HD_ 64
#define FFD 4096
#define MM  (BB*SS)   // 4096

// ---------------- scratch (allocation-free) ----------------
static __device__ float g_h   [MM*EE];    // rmsnorm out (reused)
static __device__ float g_q   [MM*EE];    // q proj [b,s,h,d]
static __device__ float g_k   [MM*HD_];   // k proj [b,s,d]
static __device__ float g_v   [MM*HD_];   // v proj
static __device__ float g_att [MM*EE];    // attention out [b,s,h*d]
static __device__ float g_x1  [MM*EE];    // after o-proj + residual
static __device__ float g_gate[MM*FFD];   // gelu(h@wg+bg)
static __device__ float g_hu  [MM*FFD];   // up * gate

// ---------------- rmsnorm ----------------
__global__ void rmsnorm_kernel(const float* __restrict__ x, const float* __restrict__ g,
                               float* __restrict__ out) {
    int row = blockIdx.x;
    const float* xr = x + (size_t)row * EE;
    float v[4];
    float s = 0.f;
#pragma unroll
    for (int i = 0; i < 4; i++) { v[i] = xr[threadIdx.x + i*256]; s += v[i]*v[i]; }
    __shared__ float red[8];
#pragma unroll
    for (int o = 16; o > 0; o >>= 1) s += __shfl_xor_sync(0xffffffffu, s, o);
    if ((threadIdx.x & 31) == 0) red[threadIdx.x >> 5] = s;
    __syncthreads();
    if (threadIdx.x < 8) {
        float t = red[threadIdx.x];
#pragma unroll
        for (int o = 4; o > 0; o >>= 1) t += __shfl_xor_sync(0xffu, t, o);
        if (threadIdx.x == 0) red[0] = t;
    }
    __syncthreads();
    float ms = red[0] * (1.0f / EE);
    float r  = rsqrtf(ms + 1.1920929e-7f);
#pragma unroll
    for (int i = 0; i < 4; i++) {
        int c = threadIdx.x + i*256;
        out[(size_t)row*EE + c] = v[i] * r * g[c];
    }
}

// ---------------- RoPE (in-place) ----------------
// t layout: [B, S, nH, 64], pos = s, half = 32
__global__ void rope_kernel(float* __restrict__ t, int nH, int total) {
    int idx = blockIdx.x * blockDim.x + threadIdx.x;
    if (idx >= total) return;
    int j    = idx & 31;
    int rest = idx >> 5;
    int h    = rest % nH;
    int row  = rest / nH;        // b*S + s
    int s    = row % SS;
    float inv = powf(10000.0f, -(float)j * (1.0f/32.0f));
    float ang = (float)s * inv;
    float c = cosf(ang), sn = sinf(ang);
    size_t base = ((size_t)row * nH + h) * 64;
    float t1 = t[base + j], t2 = t[base + 32 + j];
    t[base + j]      = t1*c  - t2*sn;
    t[base + 32 + j] = t1*sn + t2*c;
}

// ---------------- SGEMM 128x128x8, 8x8 microtile ----------------
// EPI: 0 = +bias; 1 = +bias+extra(residual); 2 = gelu(+bias); 3 = (+bias)*extra
template<int EPI>
__global__ void __launch_bounds__(256)
sgemm128(const float* __restrict__ A, const float* __restrict__ W,
         const float* __restrict__ bias, const float* __restrict__ extra,
         float* __restrict__ C, int N, int K) {
    __shared__ float As[8][132];
    __shared__ float Ws[8][128];
    const int tid = threadIdx.x;
    const int tx = tid & 15, ty = tid >> 4;
    const int row0 = blockIdx.y * 128, col0 = blockIdx.x * 128;

    const int ar = tid >> 1;          // 0..127
    const int ac = (tid & 1) * 4;     // 0 or 4
    const int wr = tid >> 5;          // 0..7
    const int wc = (tid & 31) * 4;    // 0..124

    const float* Aptr = A + (size_t)(row0 + ar) * K + ac;
    const float* Wptr = W + (size_t)wr * N + col0 + wc;

    float acc[8][8];
#pragma unroll
    for (int i = 0; i < 8; i++)
#pragma unroll
        for (int j = 0; j < 8; j++) acc[i][j] = 0.f;

    for (int kt = 0; kt < K; kt += 8) {
        float4 a4 = *(const float4*)(Aptr + kt);
        float4 w4 = *(const float4*)(Wptr + (size_t)kt * N);
        __syncthreads();
        As[ac+0][ar] = a4.x; As[ac+1][ar] = a4.y;
        As[ac+2][ar] = a4.z; As[ac+3][ar] = a4.w;
        *(float4*)&Ws[wr][wc] = w4;
        __syncthreads();
#pragma unroll
        for (int kk = 0; kk < 8; kk++) {
            float a_[8], b_[8];
#pragma unroll
            for (int i = 0; i < 8; i++) a_[i] = As[kk][ty*8 + i];
#pragma unroll
            for (int j = 0; j < 8; j++) b_[j] = Ws[kk][tx*8 + j];
#pragma unroll
            for (int i = 0; i < 8; i++)
#pragma unroll
                for (int j = 0; j < 8; j++)
                    acc[i][j] = fmaf(a_[i], b_[j], acc[i][j]);
        }
    }

#pragma unroll
    for (int i = 0; i < 8; i++) {
        int r = row0 + ty*8 + i;
#pragma unroll
        for (int j = 0; j < 8; j++) {
            int c = col0 + tx*8 + j;
            float va = acc[i][j] + bias[c];
            if (EPI == 1) va += extra[(size_t)r * N + c];
            else if (EPI == 2) va = 0.5f * va * (1.0f + erff(va * 0.7071067811865476f));
            else if (EPI == 3) va *= extra[(size_t)r * N + c];
            C[(size_t)r * N + c] = va;
        }
    }
}

// ---------------- SGEMM 64x64x16 (for N=64 K/V projections) ----------------
__global__ void __launch_bounds__(256)
sgemm64(const float* __restrict__ A, const float* __restrict__ W,
        const float* __restrict__ bias, float* __restrict__ C, int N, int K) {
    __shared__ float As[16][68];
    __shared__ float Ws[16][64];
    const int tid = threadIdx.x;
    const int tx = tid & 15, ty = tid >> 4;
    const int row0 = blockIdx.y * 64, col0 = blockIdx.x * 64;

    const int ar = tid >> 2;          // 0..63
    const int ac = (tid & 3) * 4;     // 0..12
    const int wr = tid >> 4;          // 0..15
    const int wc = (tid & 15) * 4;    // 0..60

    float acc[4][4];
#pragma unroll
    for (int i = 0; i < 4; i++)
#pragma unroll
        for (int j = 0; j < 4; j++) acc[i][j] = 0.f;

    for (int kt = 0; kt < K; kt += 16) {
        float4 a4 = *(const float4*)(A + (size_t)(row0 + ar) * K + kt + ac);
        float4 w4 = *(const float4*)(W + (size_t)(kt + wr) * N + col0 + wc);
        __syncthreads();
        As[ac+0][ar] = a4.x; As[ac+1][ar] = a4.y;
        As[ac+2][ar] = a4.z; As[ac+3][ar] = a4.w;
        *(float4*)&Ws[wr][wc] = w4;
        __syncthreads();
#pragma unroll
        for (int kk = 0; kk < 16; kk++) {
            float a_[4], b_[4];
#pragma unroll
            for (int i = 0; i < 4; i++) a_[i] = As[kk][ty*4 + i];
#pragma unroll
            for (int j = 0; j < 4; j++) b_[j] = Ws[kk][tx*4 + j];
#pragma unroll
            for (int i = 0; i < 4; i++)
#pragma unroll
                for (int j = 0; j < 4; j++)
                    acc[i][j] = fmaf(a_[i], b_[j], acc[i][j]);
        }
    }
#pragma unroll
    for (int i = 0; i < 4; i++) {
        int r = row0 + ty*4 + i;
#pragma unroll
        for (int j = 0; j < 4; j++) {
            int c = col0 + tx*4 + j;
            C[(size_t)r * N + c] = acc[i][j] + bias[c];
        }
    }
}

// ---------------- Flash attention (MQA, causal, HD=64) ----------------
// grid: (S/64, B*H), 256 threads. q:[b,s,h,64], k/v:[b,s,64], out:[b,s,h*64]
#define ATP 68
__global__ void __launch_bounds__(256)
attn_kernel(const float* __restrict__ q, const float* __restrict__ k,
            const float* __restrict__ v, float* __restrict__ out) {
    const int bh = blockIdx.y;
    const int b = bh >> 4, h = bh & 15;
    const int qb = blockIdx.x;
    const int tid = threadIdx.x;
    const int tx = tid & 15, ty = tid >> 4;

    extern __shared__ float sm[];
    float* qs = sm;               // d-major: qs[d*ATP + row]
    float* ks = sm +     64*ATP;  // d-major: ks[d*ATP + key]; reused as P[row][key]
    float* vs = sm + 2 * 64*ATP;  // row-major: vs[key*ATP + dim]

    const size_t qbase = ((size_t)(b*SS + qb*64)) * 1024 + h*64;
#pragma unroll
    for (int i = 0; i < 16; i++) {
        int e = tid + i*256;
        int r = e >> 6, d = e & 63;
        qs[d*ATP + r] = q[qbase + (size_t)r*1024 + d];
    }

    float m_[4], l_[4], acc[4][4];
#pragma unroll
    for (int i = 0; i < 4; i++) {
        m_[i] = -1e30f; l_[i] = 0.f;
#pragma unroll
        for (int j = 0; j < 4; j++) acc[i][j] = 0.f;
    }

    const size_t kvbase = (size_t)(b*SS) * 64;
    for (int kb = 0; kb <= qb; kb++) {
        __syncthreads();
#pragma unroll
        for (int i = 0; i < 16; i++) {
            int e = tid + i*256;
            int r = e >> 6, d = e & 63;
            float kv = k[kvbase + (size_t)(kb*64 + r)*64 + d];
            float vv = v[kvbase + (size_t)(kb*64 + r)*64 + d];
            ks[d*ATP + r] = kv;
            vs[r*ATP + d] = vv;
        }
        __syncthreads();

        // scores: S = Q K^T
        float s[4][4];
#pragma unroll
        for (int i = 0; i < 4; i++)
#pragma unroll
            for (int j = 0; j < 4; j++) s[i][j] = 0.f;
#pragma unroll 8
        for (int d = 0; d < 64; d++) {
            float4 q4 = *(const float4*)&qs[d*ATP + ty*4];
            float4 k4 = *(const float4*)&ks[d*ATP + tx*4];
            float qa[4] = {q4.x, q4.y, q4.z, q4.w};
            float ka[4] = {k4.x, k4.y, k4.z, k4.w};
#pragma unroll
            for (int i = 0; i < 4; i++)
#pragma unroll
                for (int j = 0; j < 4; j++)
                    s[i][j] = fmaf(qa[i], ka[j], s[i][j]);
        }

        // scale + causal mask + online softmax update
#pragma unroll
        for (int i = 0; i < 4; i++) {
            int grow = qb*64 + ty*4 + i;
#pragma unroll
            for (int j = 0; j < 4; j++) {
                int gcol = kb*64 + tx*4 + j;
                s[i][j] = (gcol <= grow) ? s[i][j] * 0.125f : -1e30f;
            }
            float mx = fmaxf(fmaxf(s[i][0], s[i][1]), fmaxf(s[i][2], s[i][3]));
#pragma unroll
            for (int o = 1; o < 16; o <<= 1)
                mx = fmaxf(mx, __shfl_xor_sync(0xffffffffu, mx, o, 16));
            float mnew = fmaxf(m_[i], mx);
            float ps = 0.f;
#pragma unroll
            for (int j = 0; j < 4; j++) { s[i][j] = __expf(s[i][j] - mnew); ps += s[i][j]; }
#pragma unroll
            for (int o = 1; o < 16; o <<= 1)
                ps += __shfl_xor_sync(0xffffffffu, ps, o, 16);
            float alpha = __expf(m_[i] - mnew);
            l_[i] = l_[i] * alpha + ps;
            m_[i] = mnew;
#pragma unroll
            for (int j = 0; j < 4; j++) acc[i][j] *= alpha;
        }
        __syncthreads();                 // all done reading ks as K
#pragma unroll
        for (int i = 0; i < 4; i++)
#pragma unroll
            for (int j = 0; j < 4; j++)
                ks[(ty*4 + i)*ATP + tx*4 + j] = s[i][j];   // P row-major
        __syncthreads();

        // acc += P @ V
#pragma unroll 4
        for (int key = 0; key < 64; key += 4) {
            float4 p4[4], v4[4];
#pragma unroll
            for (int i = 0; i < 4; i++) p4[i] = *(const float4*)&ks[(ty*4 + i)*ATP + key];
#pragma unroll
            for (int t = 0; t < 4; t++) v4[t] = *(const float4*)&vs[(key + t)*ATP + tx*4];
#pragma unroll
            for (int i = 0; i < 4; i++) {
                float pw[4] = {p4[i].x, p4[i].y, p4[i].z, p4[i].w};
#pragma unroll
                for (int t = 0; t < 4; t++) {
                    acc[i][0] = fmaf(pw[t], v4[t].x, acc[i][0]);
                    acc[i][1] = fmaf(pw[t], v4[t].y, acc[i][1]);
                    acc[i][2] = fmaf(pw[t], v4[t].z, acc[i][2]);
                    acc[i][3] = fmaf(pw[t], v4[t].w, acc[i][3]);
                }
            }
        }
    }

    const size_t obase = ((size_t)(b*SS + qb*64)) * 1024 + h*64;
#pragma unroll
    for (int i = 0; i < 4; i++) {
        float inv = 1.0f / l_[i];
        int r = ty*4 + i;
#pragma unroll
        for (int j = 0; j < 4; j++)
            out[obase + (size_t)r*1024 + tx*4 + j] = acc[i][j] * inv;
    }
}

// ---------------- launch ----------------
extern "C" void kernel_launch(void* const* d_in, const int* in_sizes, int n_in,
                              void* d_out, int out_size) {
    const float* x  = (const float*)d_in[0];
    const float* wq = (const float*)d_in[1];
    const float* bq = (const float*)d_in[2];
    const float* wk = (const float*)d_in[3];
    const float* bk = (const float*)d_in[4];
    const float* wv = (const float*)d_in[5];
    const float* bv = (const float*)d_in[6];
    const float* wo = (const float*)d_in[7];
    const float* bo = (const float*)d_in[8];
    const float* wg = (const float*)d_in[9];
    const float* bg = (const float*)d_in[10];
    const float* wu = (const float*)d_in[11];
    const float* bu = (const float*)d_in[12];
    const float* wd = (const float*)d_in[13];
    const float* bd = (const float*)d_in[14];
    const float* g1 = (const float*)d_in[15];
    const float* g2 = (const float*)d_in[16];
    float* out = (float*)d_out;

    float *h, *qb_, *kb_, *vb_, *att, *x1, *gate, *hu;
    cudaGetSymbolAddress((void**)&h,    g_h);
    cudaGetSymbolAddress((void**)&qb_,  g_q);
    cudaGetSymbolAddress((void**)&kb_,  g_k);
    cudaGetSymbolAddress((void**)&vb_,  g_v);
    cudaGetSymbolAddress((void**)&att,  g_att);
    cudaGetSymbolAddress((void**)&x1,   g_x1);
    cudaGetSymbolAddress((void**)&gate, g_gate);
    cudaGetSymbolAddress((void**)&hu,   g_hu);

    const int ATTN_SMEM = 3 * 64 * ATP * 4;   // 52224 B
    cudaFuncSetAttribute(attn_kernel, cudaFuncAttributeMaxDynamicSharedMemorySize, ATTN_SMEM);

    // 1) rmsnorm(x, g1) -> h
    rmsnorm_kernel<<<MM, 256>>>(x, g1, h);
    // 2) projections
    sgemm128<0><<<dim3(EE/128, MM/128), 256>>>(h, wq, bq, nullptr, qb_, EE, EE);
    sgemm64   <<<dim3(1,      MM/64 ), 256>>>(h, wk, bk, kb_, HD_, EE);
    sgemm64   <<<dim3(1,      MM/64 ), 256>>>(h, wv, bv, vb_, HD_, EE);
    // 3) RoPE
    rope_kernel<<<(MM*HH*32 + 255)/256, 256>>>(qb_, HH, MM*HH*32);
    rope_kernel<<<(MM*32    + 255)/256, 256>>>(kb_, 1,  MM*32);
    // 4) attention
    attn_kernel<<<dim3(SS/64, BB*HH), 256, ATTN_SMEM>>>(qb_, kb_, vb_, att);
    // 5) o-proj + residual(x)
    sgemm128<1><<<dim3(EE/128, MM/128), 256>>>(att, wo, bo, x, x1, EE, EE);
    // 6) rmsnorm(x1, g2) -> h
    rmsnorm_kernel<<<MM, 256>>>(x1, g2, h);
    // 7) gate = gelu(h@wg+bg)
    sgemm128<2><<<dim3(FFD/128, MM/128), 256>>>(h, wg, bg, nullptr, gate, FFD, EE);
    // 8) hu = (h@wu+bu) * gate
    sgemm128<3><<<dim3(FFD/128, MM/128), 256>>>(h, wu, bu, gate, hu, FFD, EE);
    // 9) out = hu@wd + bd + x1
    sgemm128<1><<<dim3(EE/128, MM/128), 256>>>(hu, wd, bd, x1, out, EE, FFD);
}

// round 3
// speedup vs baseline: 2.4164x; 2.4164x over previous
#include <cuda_runtime.h>
#include <stdint.h>
#include <math.h>

#define BB  2
#define SS  2048
#define EE  1024
#define HH  16
#define HD_ 64
#define FFD 4096
#define MM  (BB*SS)   // 4096

// ---------------- scratch (allocation-free) ----------------
static __device__ float g_h   [MM*EE];
static __device__ float g_q   [MM*EE];
static __device__ float g_k   [MM*HD_];
static __device__ float g_v   [MM*HD_];
static __device__ float g_att [MM*EE];
static __device__ float g_x1  [MM*EE];
static __device__ float g_gate[MM*FFD];
static __device__ float g_hu  [MM*FFD];
static __device__ float g_wkv [EE*128];
static __device__ float g_bkv [128];

// =================== helpers ===================
__device__ __forceinline__ uint32_t smem_u32(const void* p) {
    uint32_t a;
    asm("{ .reg .u64 t; cvta.to.shared.u64 t, %1; cvt.u32.u64 %0, t; }"
        : "=r"(a) : "l"(p));
    return a;
}
__device__ __forceinline__ uint32_t f2tf(float f) {
    uint32_t r; asm("cvt.rna.tf32.f32 %0, %1;" : "=r"(r) : "f"(f)); return r;
}
__device__ __forceinline__ float lds_f(uint32_t a) {
    float v; asm volatile("ld.shared.f32 %0, [%1];" : "=f"(v) : "r"(a)); return v;
}
__device__ __forceinline__ void cpasync16(uint32_t sp, const void* gp) {
    asm volatile("cp.async.ca.shared.global [%0], [%1], 16;" :: "r"(sp), "l"(gp) : "memory");
}
__device__ __forceinline__ void mma_tf32(float* d, const uint32_t* a, const uint32_t* b) {
    asm volatile(
        "mma.sync.aligned.m16n8k8.row.col.f32.tf32.tf32.f32 "
        "{%0,%1,%2,%3}, {%4,%5,%6,%7}, {%8,%9}, {%0,%1,%2,%3};"
        : "+f"(d[0]), "+f"(d[1]), "+f"(d[2]), "+f"(d[3])
        : "r"(a[0]), "r"(a[1]), "r"(a[2]), "r"(a[3]), "r"(b[0]), "r"(b[1]));
}

// smem layout (bytes, per buffer):
//   A: 128 rows x 36 words  -> 18432 B   (pad 36: bank 4r+c unique)
//   B:  32 rows x 136 words -> 17408 B   (pad 136: bank 8k+n unique)
#define A_BUF_BYTES 18432
#define B_BUF_BYTES 17408
#define B_REGION    (2 * A_BUF_BYTES)
#define GEMM_SMEM   (2 * (A_BUF_BYTES + B_BUF_BYTES))   // 71680

// =================== tf32 mma.sync GEMM ===================
// C[M,N] = A[M,K] @ W[K,N] + bias, epilogue EPI:
// 0=+bias; 1=+bias+extra; 2=gelu(+bias); 3=(+bias)*extra; 4=KV split
template<int EPI>
__global__ void __launch_bounds__(256, 2)
mma_gemm(const float* __restrict__ A, const float* __restrict__ W,
         const float* __restrict__ bias, const float* extra,
         float* __restrict__ C, int N, int K) {
    extern __shared__ char dyn[];
    const uint32_t smem_base = smem_u32(dyn);

    const int tid  = threadIdx.x;
    const int lane = tid & 31;
    const int warp = tid >> 5;
    const int wr = warp & 1;          // 0/1 : 64-row half
    const int wc = warp >> 1;         // 0..3: 32-col quarter
    const int row0 = blockIdx.y * 128, col0 = blockIdx.x * 128;

    const int rp = lane >> 2;         // 0..7
    const int cp = lane & 3;          // 0..3

    // per-thread fragment base offsets (bytes)
    const uint32_t a_off = (uint32_t)(((wr*64 + rp) * 36 + cp) * 4);
    const uint32_t b_off = (uint32_t)((cp * 136 + wc*32 + rp) * 4);

    float acc[4][4][4];
#pragma unroll
    for (int i = 0; i < 4; i++)
#pragma unroll
        for (int j = 0; j < 4; j++)
#pragma unroll
            for (int q = 0; q < 4; q++) acc[i][j][q] = 0.f;

    auto issue_slab = [&](int buf, int kb) {
        uint32_t as = smem_base + (uint32_t)buf * A_BUF_BYTES;
        uint32_t bs = smem_base + B_REGION + (uint32_t)buf * B_BUF_BYTES;
#pragma unroll
        for (int i = 0; i < 4; i++) {
            int f = tid + i * 256;
            int r = f >> 3, c4 = f & 7;
            cpasync16(as + (uint32_t)(r * 144 + c4 * 16),
                      A + (size_t)(row0 + r) * K + kb + c4 * 4);
        }
#pragma unroll
        for (int i = 0; i < 4; i++) {
            int f = tid + i * 256;
            int k = f >> 5, c4 = f & 31;
            cpasync16(bs + (uint32_t)(k * 544 + c4 * 16),
                      W + (size_t)(kb + k) * N + col0 + c4 * 4);
        }
        asm volatile("cp.async.commit_group;" ::: "memory");
    };

    auto compute = [&](int buf) {
        const uint32_t as = smem_base + (uint32_t)buf * A_BUF_BYTES + a_off;
        const uint32_t bs = smem_base + B_REGION + (uint32_t)buf * B_BUF_BYTES + b_off;
#pragma unroll
        for (int ks = 0; ks < 4; ks++) {
            uint32_t af[4][4];
#pragma unroll
            for (int mt = 0; mt < 4; mt++) {
                uint32_t base = as + (uint32_t)(mt * 2304 + ks * 32);
                af[mt][0] = f2tf(lds_f(base));
                af[mt][1] = f2tf(lds_f(base + 1152));        // +8 rows
                af[mt][2] = f2tf(lds_f(base + 16));          // +4 k
                af[mt][3] = f2tf(lds_f(base + 1152 + 16));
            }
            uint32_t bf[4][2];
#pragma unroll
            for (int nt = 0; nt < 4; nt++) {
                uint32_t base = bs + (uint32_t)(nt * 32 + ks * 4352);
                bf[nt][0] = f2tf(lds_f(base));
                bf[nt][1] = f2tf(lds_f(base + 2176));        // +4 k rows
            }
#pragma unroll
            for (int mt = 0; mt < 4; mt++)
#pragma unroll
                for (int nt = 0; nt < 4; nt++)
                    mma_tf32(acc[mt][nt], af[mt], bf[nt]);
        }
    };

    const int nk = K >> 5;
    issue_slab(0, 0);
    for (int kt = 0; kt < nk; kt++) {
        int buf = kt & 1;
        if (kt + 1 < nk) {
            issue_slab(buf ^ 1, (kt + 1) << 5);
            asm volatile("cp.async.wait_group 1;" ::: "memory");
        } else {
            asm volatile("cp.async.wait_group 0;" ::: "memory");
        }
        __syncthreads();
        compute(buf);
        __syncthreads();
    }

    // ---------------- epilogue ----------------
#pragma unroll
    for (int mt = 0; mt < 4; mt++) {
#pragma unroll
        for (int nt = 0; nt < 4; nt++) {
            int row = row0 + wr*64 + mt*16 + rp;
            int col = col0 + wc*32 + nt*8 + 2*cp;
#pragma unroll
            for (int half = 0; half < 2; half++) {
                int r = row + half * 8;
                float v0 = acc[mt][nt][half*2 + 0] + bias[col];
                float v1 = acc[mt][nt][half*2 + 1] + bias[col + 1];
                if (EPI == 4) {
                    float2 o = make_float2(v0, v1);
                    if (col < 64) *(float2*)&C[(size_t)r * 64 + col] = o;
                    else *(float2*)&((float*)extra)[(size_t)r * 64 + col - 64] = o;
                } else {
                    size_t gi = (size_t)r * N + col;
                    if (EPI == 1) { float2 e = *(const float2*)&extra[gi]; v0 += e.x; v1 += e.y; }
                    else if (EPI == 2) {
                        v0 = 0.5f * v0 * (1.0f + erff(v0 * 0.7071067811865476f));
                        v1 = 0.5f * v1 * (1.0f + erff(v1 * 0.7071067811865476f));
                    } else if (EPI == 3) { float2 e = *(const float2*)&extra[gi]; v0 *= e.x; v1 *= e.y; }
                    *(float2*)&C[gi] = make_float2(v0, v1);
                }
            }
        }
    }
}

// ---------------- rmsnorm ----------------
__global__ void rmsnorm_kernel(const float* __restrict__ x, const float* __restrict__ g,
                               float* __restrict__ out) {
    int row = blockIdx.x;
    const float* xr = x + (size_t)row * EE;
    float v[4];
    float s = 0.f;
#pragma unroll
    for (int i = 0; i < 4; i++) { v[i] = xr[threadIdx.x + i*256]; s += v[i]*v[i]; }
    __shared__ float red[8];
#pragma unroll
    for (int o = 16; o > 0; o >>= 1) s += __shfl_xor_sync(0xffffffffu, s, o);
    if ((threadIdx.x & 31) == 0) red[threadIdx.x >> 5] = s;
    __syncthreads();
    if (threadIdx.x < 8) {
        float t = red[threadIdx.x];
#pragma unroll
        for (int o = 4; o > 0; o >>= 1) t += __shfl_xor_sync(0xffu, t, o);
        if (threadIdx.x == 0) red[0] = t;
    }
    __syncthreads();
    float ms = red[0] * (1.0f / EE);
    float r  = rsqrtf(ms + 1.1920929e-7f);
#pragma unroll
    for (int i = 0; i < 4; i++) {
        int c = threadIdx.x + i*256;
        out[(size_t)row*EE + c] = v[i] * r * g[c];
    }
}

// ---------------- concat wk|wv, bk|bv ----------------
__global__ void concat_wkv_kernel(const float* __restrict__ wk, const float* __restrict__ wv,
                                  const float* __restrict__ bk, const float* __restrict__ bv,
                                  float* __restrict__ wkv, float* __restrict__ bkv) {
    int i = blockIdx.x * blockDim.x + threadIdx.x;
    if (i < EE * 128) {
        int k = i >> 7, c = i & 127;
        wkv[i] = (c < 64) ? wk[k * 64 + c] : wv[k * 64 + c - 64];
    }
    if (i < 128) bkv[i] = (i < 64) ? bk[i] : bv[i - 64];
}

// ---------------- RoPE (in-place) ----------------
__global__ void rope_kernel(float* __restrict__ t, int nH, int total) {
    int idx = blockIdx.x * blockDim.x + threadIdx.x;
    if (idx >= total) return;
    int j    = idx & 31;
    int rest = idx >> 5;
    int h    = rest % nH;
    int row  = rest / nH;
    int s    = row % SS;
    float inv = powf(10000.0f, -(float)j * (1.0f/32.0f));
    float ang = (float)s * inv;
    float c = cosf(ang), sn = sinf(ang);
    size_t base = ((size_t)row * nH + h) * 64;
    float t1 = t[base + j], t2 = t[base + 32 + j];
    t[base + j]      = t1*c  - t2*sn;
    t[base + 32 + j] = t1*sn + t2*c;
}

// ---------------- Flash attention (MQA, causal, HD=64) ----------------
#define ATP 68
__global__ void __launch_bounds__(256)
attn_kernel(const float* __restrict__ q, const float* __restrict__ k,
            const float* __restrict__ v, float* __restrict__ out) {
    const int bh = blockIdx.y;
    const int b = bh >> 4, h = bh & 15;
    const int qb = blockIdx.x;
    const int tid = threadIdx.x;
    const int tx = tid & 15, ty = tid >> 4;

    extern __shared__ float sm[];
    float* qs = sm;
    float* ks = sm +     64*ATP;
    float* vs = sm + 2 * 64*ATP;

    const size_t qbase = ((size_t)(b*SS + qb*64)) * 1024 + h*64;
#pragma unroll
    for (int i = 0; i < 16; i++) {
        int e = tid + i*256;
        int r = e >> 6, d = e & 63;
        qs[d*ATP + r] = q[qbase + (size_t)r*1024 + d];
    }

    float m_[4], l_[4], acc[4][4];
#pragma unroll
    for (int i = 0; i < 4; i++) {
        m_[i] = -1e30f; l_[i] = 0.f;
#pragma unroll
        for (int j = 0; j < 4; j++) acc[i][j] = 0.f;
    }

    const size_t kvbase = (size_t)(b*SS) * 64;
    for (int kb = 0; kb <= qb; kb++) {
        __syncthreads();
#pragma unroll
        for (int i = 0; i < 16; i++) {
            int e = tid + i*256;
            int r = e >> 6, d = e & 63;
            float kv = k[kvbase + (size_t)(kb*64 + r)*64 + d];
            float vv = v[kvbase + (size_t)(kb*64 + r)*64 + d];
            ks[d*ATP + r] = kv;
            vs[r*ATP + d] = vv;
        }
        __syncthreads();

        float s[4][4];
#pragma unroll
        for (int i = 0; i < 4; i++)
#pragma unroll
            for (int j = 0; j < 4; j++) s[i][j] = 0.f;
#pragma unroll 8
        for (int d = 0; d < 64; d++) {
            float4 q4 = *(const float4*)&qs[d*ATP + ty*4];
            float4 k4 = *(const float4*)&ks[d*ATP + tx*4];
            float qa[4] = {q4.x, q4.y, q4.z, q4.w};
            float ka[4] = {k4.x, k4.y, k4.z, k4.w};
#pragma unroll
            for (int i = 0; i < 4; i++)
#pragma unroll
                for (int j = 0; j < 4; j++)
                    s[i][j] = fmaf(qa[i], ka[j], s[i][j]);
        }

#pragma unroll
        for (int i = 0; i < 4; i++) {
            int grow = qb*64 + ty*4 + i;
#pragma unroll
            for (int j = 0; j < 4; j++) {
                int gcol = kb*64 + tx*4 + j;
                s[i][j] = (gcol <= grow) ? s[i][j] * 0.125f : -1e30f;
            }
            float mx = fmaxf(fmaxf(s[i][0], s[i][1]), fmaxf(s[i][2], s[i][3]));
#pragma unroll
            for (int o = 1; o < 16; o <<= 1)
                mx = fmaxf(mx, __shfl_xor_sync(0xffffffffu, mx, o, 16));
            float mnew = fmaxf(m_[i], mx);
            float ps = 0.f;
#pragma unroll
            for (int j = 0; j < 4; j++) { s[i][j] = __expf(s[i][j] - mnew); ps += s[i][j]; }
#pragma unroll
            for (int o = 1; o < 16; o <<= 1)
                ps += __shfl_xor_sync(0xffffffffu, ps, o, 16);
            float alpha = __expf(m_[i] - mnew);
            l_[i] = l_[i] * alpha + ps;
            m_[i] = mnew;
#pragma unroll
            for (int j = 0; j < 4; j++) acc[i][j] *= alpha;
        }
        __syncthreads();
#pragma unroll
        for (int i = 0; i < 4; i++)
#pragma unroll
            for (int j = 0; j < 4; j++)
                ks[(ty*4 + i)*ATP + tx*4 + j] = s[i][j];
        __syncthreads();

#pragma unroll 4
        for (int key = 0; key < 64; key += 4) {
            float4 p4[4], v4[4];
#pragma unroll
            for (int i = 0; i < 4; i++) p4[i] = *(const float4*)&ks[(ty*4 + i)*ATP + key];
#pragma unroll
            for (int t = 0; t < 4; t++) v4[t] = *(const float4*)&vs[(key + t)*ATP + tx*4];
#pragma unroll
            for (int i = 0; i < 4; i++) {
                float pw[4] = {p4[i].x, p4[i].y, p4[i].z, p4[i].w};
#pragma unroll
                for (int t = 0; t < 4; t++) {
                    acc[i][0] = fmaf(pw[t], v4[t].x, acc[i][0]);
                    acc[i][1] = fmaf(pw[t], v4[t].y, acc[i][1]);
                    acc[i][2] = fmaf(pw[t], v4[t].z, acc[i][2]);
                    acc[i][3] = fmaf(pw[t], v4[t].w, acc[i][3]);
                }
            }
        }
    }

    const size_t obase = ((size_t)(b*SS + qb*64)) * 1024 + h*64;
#pragma unroll
    for (int i = 0; i < 4; i++) {
        float inv = 1.0f / l_[i];
        int r = ty*4 + i;
#pragma unroll
        for (int j = 0; j < 4; j++)
            out[obase + (size_t)r*1024 + tx*4 + j] = acc[i][j] * inv;
    }
}

// ---------------- launch ----------------
extern "C" void kernel_launch(void* const* d_in, const int* in_sizes, int n_in,
                              void* d_out, int out_size) {
    const float* x  = (const float*)d_in[0];
    const float* wq = (const float*)d_in[1];
    const float* bq = (const float*)d_in[2];
    const float* wk = (const float*)d_in[3];
    const float* bk = (const float*)d_in[4];
    const float* wv = (const float*)d_in[5];
    const float* bv = (const float*)d_in[6];
    const float* wo = (const float*)d_in[7];
    const float* bo = (const float*)d_in[8];
    const float* wg = (const float*)d_in[9];
    const float* bg = (const float*)d_in[10];
    const float* wu = (const float*)d_in[11];
    const float* bu = (const float*)d_in[12];
    const float* wd = (const float*)d_in[13];
    const float* bd = (const float*)d_in[14];
    const float* g1 = (const float*)d_in[15];
    const float* g2 = (const float*)d_in[16];
    float* out = (float*)d_out;

    float *h, *qb_, *kb_, *vb_, *att, *x1, *gate, *hu, *wkv, *bkv;
    cudaGetSymbolAddress((void**)&h,    g_h);
    cudaGetSymbolAddress((void**)&qb_,  g_q);
    cudaGetSymbolAddress((void**)&kb_,  g_k);
    cudaGetSymbolAddress((void**)&vb_,  g_v);
    cudaGetSymbolAddress((void**)&att,  g_att);
    cudaGetSymbolAddress((void**)&x1,   g_x1);
    cudaGetSymbolAddress((void**)&gate, g_gate);
    cudaGetSymbolAddress((void**)&hu,   g_hu);
    cudaGetSymbolAddress((void**)&wkv,  g_wkv);
    cudaGetSymbolAddress((void**)&bkv,  g_bkv);

    cudaFuncSetAttribute(mma_gemm<0>, cudaFuncAttributeMaxDynamicSharedMemorySize, GEMM_SMEM);
    cudaFuncSetAttribute(mma_gemm<1>, cudaFuncAttributeMaxDynamicSharedMemorySize, GEMM_SMEM);
    cudaFuncSetAttribute(mma_gemm<2>, cudaFuncAttributeMaxDynamicSharedMemorySize, GEMM_SMEM);
    cudaFuncSetAttribute(mma_gemm<3>, cudaFuncAttributeMaxDynamicSharedMemorySize, GEMM_SMEM);
    cudaFuncSetAttribute(mma_gemm<4>, cudaFuncAttributeMaxDynamicSharedMemorySize, GEMM_SMEM);
    const int ATTN_SMEM = 3 * 64 * ATP * 4;   // 52224 B
    cudaFuncSetAttribute(attn_kernel, cudaFuncAttributeMaxDynamicSharedMemorySize, ATTN_SMEM);

    // 1) rmsnorm(x, g1) -> h ; concat kv weights
    rmsnorm_kernel<<<MM, 256>>>(x, g1, h);
    concat_wkv_kernel<<<(EE*128 + 255)/256, 256>>>(wk, wv, bk, bv, wkv, bkv);
    // 2) projections (tensor cores via mma.sync tf32)
    mma_gemm<0><<<dim3(EE/128, MM/128), 256, GEMM_SMEM>>>(h, wq, bq, nullptr, qb_, EE, EE);
    mma_gemm<4><<<dim3(1,      MM/128), 256, GEMM_SMEM>>>(h, wkv, bkv, (const float*)vb_, kb_, 128, EE);
    // 3) RoPE
    rope_kernel<<<(MM*HH*32 + 255)/256, 256>>>(qb_, HH, MM*HH*32);
    rope_kernel<<<(MM*32    + 255)/256, 256>>>(kb_, 1,  MM*32);
    // 4) attention
    attn_kernel<<<dim3(SS/64, BB*HH), 256, ATTN_SMEM>>>(qb_, kb_, vb_, att);
    // 5) o-proj + residual(x)
    mma_gemm<1><<<dim3(EE/128, MM/128), 256, GEMM_SMEM>>>(att, wo, bo, x, x1, EE, EE);
    // 6) rmsnorm(x1, g2) -> h
    rmsnorm_kernel<<<MM, 256>>>(x1, g2, h);
    // 7) gate = gelu(h@wg+bg)
    mma_gemm<2><<<dim3(FFD/128, MM/128), 256, GEMM_SMEM>>>(h, wg, bg, nullptr, gate, FFD, EE);
    // 8) hu = (h@wu+bu) * gate
    mma_gemm<3><<<dim3(FFD/128, MM/128), 256, GEMM_SMEM>>>(h, wu, bu, gate, hu, FFD, EE);
    // 9) out = hu@wd + bd + x1
    mma_gemm<1><<<dim3(EE/128, MM/128), 256, GEMM_SMEM>>>(hu, wd, bd, x1, out, EE, FFD);
}

// round 4
// speedup vs baseline: 2.5941x; 1.0735x over previous
#include <cuda_runtime.h>
#include <stdint.h>
#include <math.h>

#define BB  2
#define SS  2048
#define EE  1024
#define HH  16
#define HD_ 64
#define FFD 4096
#define MM  (BB*SS)   // 4096

// ---------------- scratch (allocation-free) ----------------
static __device__ float g_h   [MM*EE];
static __device__ float g_q   [MM*EE];
static __device__ float g_k   [MM*HD_];
static __device__ float g_v   [MM*HD_];
static __device__ float g_att [MM*EE];
static __device__ float g_x1  [MM*EE];
static __device__ float g_gate[MM*FFD];
static __device__ float g_hu  [MM*FFD];
// transposed (tf32-rounded) weights: WT[N][K]
static __device__ float g_wqT [EE*EE];
static __device__ float g_wkvT[128*EE];
static __device__ float g_woT [EE*EE];
static __device__ float g_wgT [FFD*EE];
static __device__ float g_wuT [FFD*EE];
static __device__ float g_wdT [EE*FFD];
static __device__ float g_bkv [128];

// =================== helpers ===================
__device__ __forceinline__ uint32_t smem_u32(const void* p) {
    uint32_t a;
    asm("{ .reg .u64 t; cvta.to.shared.u64 t, %1; cvt.u32.u64 %0, t; }"
        : "=r"(a) : "l"(p));
    return a;
}
__device__ __forceinline__ float f2tf_f(float f) {
    uint32_t r; asm("cvt.rna.tf32.f32 %0, %1;" : "=r"(r) : "f"(f));
    return __uint_as_float(r);
}
__device__ __forceinline__ void cpasync16(uint32_t sp, const void* gp) {
    asm volatile("cp.async.ca.shared.global [%0], [%1], 16;" :: "r"(sp), "l"(gp) : "memory");
}
__device__ __forceinline__ void ldsm4(uint32_t addr, uint32_t& r0, uint32_t& r1,
                                      uint32_t& r2, uint32_t& r3) {
    asm volatile("ldmatrix.sync.aligned.m8n8.x4.shared.b16 {%0,%1,%2,%3}, [%4];"
                 : "=r"(r0), "=r"(r1), "=r"(r2), "=r"(r3) : "r"(addr));
}
__device__ __forceinline__ void mma_tf32(float* d, const uint32_t* a, const uint32_t* b) {
    asm volatile(
        "mma.sync.aligned.m16n8k8.row.col.f32.tf32.tf32.f32 "
        "{%0,%1,%2,%3}, {%4,%5,%6,%7}, {%8,%9}, {%0,%1,%2,%3};"
        : "+f"(d[0]), "+f"(d[1]), "+f"(d[2]), "+f"(d[3])
        : "r"(a[0]), "r"(a[1]), "r"(a[2]), "r"(a[3]), "r"(b[0]), "r"(b[1]));
}

// smem: A buf = B buf = 128 rows x 36 words = 18432 B each; double buffered
#define BUF_BYTES 18432
#define B_REGION  (2 * BUF_BYTES)
#define GEMM_SMEM (4 * BUF_BYTES)   // 73728

// =================== tf32 mma.sync GEMM (ldmatrix, pre-rounded operands) ===================
// C[M,N] = A[M,K] @ WT[N,K]^T + bias. EPI: 0=+bias; 1=+bias+extra; 2=gelu; 3=(+bias)*extra,
// rounded to tf32; 4=KV split
template<int EPI>
__global__ void __launch_bounds__(256, 2)
mma_gemm(const float* __restrict__ A, const float* __restrict__ WT,
         const float* __restrict__ bias, const float* extra,
         float* __restrict__ C, int N, int K) {
    extern __shared__ char dyn[];
    const uint32_t smem_base = smem_u32(dyn);

    const int tid  = threadIdx.x;
    const int lane = tid & 31;
    const int warp = tid >> 5;
    const int wr = warp & 1;          // 0/1 : 64-row half
    const int wc = warp >> 1;         // 0..3: 32-col quarter
    const int row0 = blockIdx.y * 128, col0 = blockIdx.x * 128;

    const int rp = lane >> 2;         // 0..7
    const int cp = lane & 3;          // 0..3

    // ldmatrix per-thread base offsets (bytes)
    const uint32_t a_lm = (uint32_t)(((wr*64 + (lane & 15)) * 36 + ((lane >> 4) & 1) * 4) * 4);
    const uint32_t b_lm = (uint32_t)(((wc*32 + (lane & 7) + ((lane >> 4) & 1) * 8) * 36
                                      + ((lane >> 3) & 1) * 4) * 4);

    float acc[4][4][4];
#pragma unroll
    for (int i = 0; i < 4; i++)
#pragma unroll
        for (int j = 0; j < 4; j++)
#pragma unroll
            for (int q = 0; q < 4; q++) acc[i][j][q] = 0.f;

    auto issue_slab = [&](int buf, int kb) {
        uint32_t as = smem_base + (uint32_t)buf * BUF_BYTES;
        uint32_t bs = smem_base + B_REGION + (uint32_t)buf * BUF_BYTES;
#pragma unroll
        for (int i = 0; i < 4; i++) {
            int f = tid + i * 256;
            int r = f >> 3, c4 = f & 7;
            cpasync16(as + (uint32_t)(r * 144 + c4 * 16),
                      A + (size_t)(row0 + r) * K + kb + c4 * 4);
        }
#pragma unroll
        for (int i = 0; i < 4; i++) {
            int f = tid + i * 256;
            int r = f >> 3, c4 = f & 7;
            cpasync16(bs + (uint32_t)(r * 144 + c4 * 16),
                      WT + (size_t)(col0 + r) * K + kb + c4 * 4);
        }
        asm volatile("cp.async.commit_group;" ::: "memory");
    };

    auto compute = [&](int buf) {
        const uint32_t as = smem_base + (uint32_t)buf * BUF_BYTES + a_lm;
        const uint32_t bs = smem_base + B_REGION + (uint32_t)buf * BUF_BYTES + b_lm;
#pragma unroll
        for (int ks = 0; ks < 4; ks++) {
            uint32_t af[4][4];
#pragma unroll
            for (int mt = 0; mt < 4; mt++)
                ldsm4(as + (uint32_t)(mt * 2304 + ks * 32),
                      af[mt][0], af[mt][1], af[mt][2], af[mt][3]);
            uint32_t bf[4][2];
            ldsm4(bs + (uint32_t)(ks * 32),        bf[0][0], bf[0][1], bf[1][0], bf[1][1]);
            ldsm4(bs + (uint32_t)(2304 + ks * 32), bf[2][0], bf[2][1], bf[3][0], bf[3][1]);
#pragma unroll
            for (int mt = 0; mt < 4; mt++)
#pragma unroll
                for (int nt = 0; nt < 4; nt++)
                    mma_tf32(acc[mt][nt], af[mt], bf[nt]);
        }
    };

    const int nk = K >> 5;
    issue_slab(0, 0);
    for (int kt = 0; kt < nk; kt++) {
        int buf = kt & 1;
        if (kt + 1 < nk) {
            issue_slab(buf ^ 1, (kt + 1) << 5);
            asm volatile("cp.async.wait_group 1;" ::: "memory");
        } else {
            asm volatile("cp.async.wait_group 0;" ::: "memory");
        }
        __syncthreads();
        compute(buf);
        __syncthreads();
    }

    // ---------------- epilogue ----------------
#pragma unroll
    for (int mt = 0; mt < 4; mt++) {
#pragma unroll
        for (int nt = 0; nt < 4; nt++) {
            int row = row0 + wr*64 + mt*16 + rp;
            int col = col0 + wc*32 + nt*8 + 2*cp;
#pragma unroll
            for (int half = 0; half < 2; half++) {
                int r = row + half * 8;
                float v0 = acc[mt][nt][half*2 + 0] + bias[col];
                float v1 = acc[mt][nt][half*2 + 1] + bias[col + 1];
                if (EPI == 4) {
                    float2 o = make_float2(v0, v1);
                    if (col < 64) *(float2*)&C[(size_t)r * 64 + col] = o;
                    else *(float2*)&((float*)extra)[(size_t)r * 64 + col - 64] = o;
                } else {
                    size_t gi = (size_t)r * N + col;
                    if (EPI == 1) { float2 e = *(const float2*)&extra[gi]; v0 += e.x; v1 += e.y; }
                    else if (EPI == 2) {
                        v0 = 0.5f * v0 * (1.0f + erff(v0 * 0.7071067811865476f));
                        v1 = 0.5f * v1 * (1.0f + erff(v1 * 0.7071067811865476f));
                    } else if (EPI == 3) {
                        float2 e = *(const float2*)&extra[gi];
                        v0 = f2tf_f(v0 * e.x); v1 = f2tf_f(v1 * e.y);  // hu feeds down-GEMM
                    }
                    *(float2*)&C[gi] = make_float2(v0, v1);
                }
            }
        }
    }
}

// ---------------- weight transpose + tf32 round: W[K][N] -> WT[N][K] ----------------
__global__ void wtrans_kernel(const float* __restrict__ W, float* __restrict__ WT,
                              int K, int N) {
    __shared__ float t[32][33];
    int nb = blockIdx.x * 32, kb = blockIdx.y * 32;
    int tx = threadIdx.x, ty = threadIdx.y;   // 32 x 8
#pragma unroll
    for (int j = 0; j < 4; j++)
        t[ty + j*8][tx] = W[(size_t)(kb + ty + j*8) * N + nb + tx];
    __syncthreads();
#pragma unroll
    for (int j = 0; j < 4; j++)
        WT[(size_t)(nb + ty + j*8) * K + kb + tx] = f2tf_f(t[tx][ty + j*8]);
}

__global__ void bkv_kernel(const float* __restrict__ bk, const float* __restrict__ bv,
                           float* __restrict__ bkv) {
    int i = threadIdx.x;
    bkv[i] = (i < 64) ? bk[i] : bv[i - 64];
}

// ---------------- rmsnorm (tf32-rounded output: feeds GEMMs only) ----------------
__global__ void rmsnorm_kernel(const float* __restrict__ x, const float* __restrict__ g,
                               float* __restrict__ out) {
    int row = blockIdx.x;
    const float* xr = x + (size_t)row * EE;
    float v[4];
    float s = 0.f;
#pragma unroll
    for (int i = 0; i < 4; i++) { v[i] = xr[threadIdx.x + i*256]; s += v[i]*v[i]; }
    __shared__ float red[8];
#pragma unroll
    for (int o = 16; o > 0; o >>= 1) s += __shfl_xor_sync(0xffffffffu, s, o);
    if ((threadIdx.x & 31) == 0) red[threadIdx.x >> 5] = s;
    __syncthreads();
    if (threadIdx.x < 8) {
        float t = red[threadIdx.x];
#pragma unroll
        for (int o = 4; o > 0; o >>= 1) t += __shfl_xor_sync(0xffu, t, o);
        if (threadIdx.x == 0) red[0] = t;
    }
    __syncthreads();
    float ms = red[0] * (1.0f / EE);
    float r  = rsqrtf(ms + 1.1920929e-7f);
#pragma unroll
    for (int i = 0; i < 4; i++) {
        int c = threadIdx.x + i*256;
        out[(size_t)row*EE + c] = f2tf_f(v[i] * r * g[c]);
    }
}

// ---------------- RoPE (in-place) ----------------
__global__ void rope_kernel(float* __restrict__ t, int nH, int total) {
    int idx = blockIdx.x * blockDim.x + threadIdx.x;
    if (idx >= total) return;
    int j    = idx & 31;
    int rest = idx >> 5;
    int h    = rest % nH;
    int row  = rest / nH;
    int s    = row % SS;
    float inv = powf(10000.0f, -(float)j * (1.0f/32.0f));
    float ang = (float)s * inv;
    float c = cosf(ang), sn = sinf(ang);
    size_t base = ((size_t)row * nH + h) * 64;
    float t1 = t[base + j], t2 = t[base + 32 + j];
    t[base + j]      = t1*c  - t2*sn;
    t[base + 32 + j] = t1*sn + t2*c;
}

// ---------------- Flash attention (MQA, causal, HD=64); out rounded to tf32 ----------------
#define ATP 68
__global__ void __launch_bounds__(256)
attn_kernel(const float* __restrict__ q, const float* __restrict__ k,
            const float* __restrict__ v, float* __restrict__ out) {
    const int bh = blockIdx.y;
    const int b = bh >> 4, h = bh & 15;
    const int qb = blockIdx.x;
    const int tid = threadIdx.x;
    const int tx = tid & 15, ty = tid >> 4;

    extern __shared__ float sm[];
    float* qs = sm;
    float* ks = sm +     64*ATP;
    float* vs = sm + 2 * 64*ATP;

    const size_t qbase = ((size_t)(b*SS + qb*64)) * 1024 + h*64;
#pragma unroll
    for (int i = 0; i < 16; i++) {
        int e = tid + i*256;
        int r = e >> 6, d = e & 63;
        qs[d*ATP + r] = q[qbase + (size_t)r*1024 + d];
    }

    float m_[4], l_[4], acc[4][4];
#pragma unroll
    for (int i = 0; i < 4; i++) {
        m_[i] = -1e30f; l_[i] = 0.f;
#pragma unroll
        for (int j = 0; j < 4; j++) acc[i][j] = 0.f;
    }

    const size_t kvbase = (size_t)(b*SS) * 64;
    for (int kb = 0; kb <= qb; kb++) {
        __syncthreads();
#pragma unroll
        for (int i = 0; i < 16; i++) {
            int e = tid + i*256;
            int r = e >> 6, d = e & 63;
            float kv = k[kvbase + (size_t)(kb*64 + r)*64 + d];
            float vv = v[kvbase + (size_t)(kb*64 + r)*64 + d];
            ks[d*ATP + r] = kv;
            vs[r*ATP + d] = vv;
        }
        __syncthreads();

        float s[4][4];
#pragma unroll
        for (int i = 0; i < 4; i++)
#pragma unroll
            for (int j = 0; j < 4; j++) s[i][j] = 0.f;
#pragma unroll 8
        for (int d = 0; d < 64; d++) {
            float4 q4 = *(const float4*)&qs[d*ATP + ty*4];
            float4 k4 = *(const float4*)&ks[d*ATP + tx*4];
            float qa[4] = {q4.x, q4.y, q4.z, q4.w};
            float ka[4] = {k4.x, k4.y, k4.z, k4.w};
#pragma unroll
            for (int i = 0; i < 4; i++)
#pragma unroll
                for (int j = 0; j < 4; j++)
                    s[i][j] = fmaf(qa[i], ka[j], s[i][j]);
        }

#pragma unroll
        for (int i = 0; i < 4; i++) {
            int grow = qb*64 + ty*4 + i;
#pragma unroll
            for (int j = 0; j < 4; j++) {
                int gcol = kb*64 + tx*4 + j;
                s[i][j] = (gcol <= grow) ? s[i][j] * 0.125f : -1e30f;
            }
            float mx = fmaxf(fmaxf(s[i][0], s[i][1]), fmaxf(s[i][2], s[i][3]));
#pragma unroll
            for (int o = 1; o < 16; o <<= 1)
                mx = fmaxf(mx, __shfl_xor_sync(0xffffffffu, mx, o, 16));
            float mnew = fmaxf(m_[i], mx);
            float ps = 0.f;
#pragma unroll
            for (int j = 0; j < 4; j++) { s[i][j] = __expf(s[i][j] - mnew); ps += s[i][j]; }
#pragma unroll
            for (int o = 1; o < 16; o <<= 1)
                ps += __shfl_xor_sync(0xffffffffu, ps, o, 16);
            float alpha = __expf(m_[i] - mnew);
            l_[i] = l_[i] * alpha + ps;
            m_[i] = mnew;
#pragma unroll
            for (int j = 0; j < 4; j++) acc[i][j] *= alpha;
        }
        __syncthreads();
#pragma unroll
        for (int i = 0; i < 4; i++)
#pragma unroll
            for (int j = 0; j < 4; j++)
                ks[(ty*4 + i)*ATP + tx*4 + j] = s[i][j];
        __syncthreads();

#pragma unroll 4
        for (int key = 0; key < 64; key += 4) {
            float4 p4[4], v4[4];
#pragma unroll
            for (int i = 0; i < 4; i++) p4[i] = *(const float4*)&ks[(ty*4 + i)*ATP + key];
#pragma unroll
            for (int t = 0; t < 4; t++) v4[t] = *(const float4*)&vs[(key + t)*ATP + tx*4];
#pragma unroll
            for (int i = 0; i < 4; i++) {
                float pw[4] = {p4[i].x, p4[i].y, p4[i].z, p4[i].w};
#pragma unroll
                for (int t = 0; t < 4; t++) {
                    acc[i][0] = fmaf(pw[t], v4[t].x, acc[i][0]);
                    acc[i][1] = fmaf(pw[t], v4[t].y, acc[i][1]);
                    acc[i][2] = fmaf(pw[t], v4[t].z, acc[i][2]);
                    acc[i][3] = fmaf(pw[t], v4[t].w, acc[i][3]);
                }
            }
        }
    }

    const size_t obase = ((size_t)(b*SS + qb*64)) * 1024 + h*64;
#pragma unroll
    for (int i = 0; i < 4; i++) {
        float inv = 1.0f / l_[i];
        int r = ty*4 + i;
#pragma unroll
        for (int j = 0; j < 4; j++)
            out[obase + (size_t)r*1024 + tx*4 + j] = f2tf_f(acc[i][j] * inv);
    }
}

// ---------------- launch ----------------
extern "C" void kernel_launch(void* const* d_in, const int* in_sizes, int n_in,
                              void* d_out, int out_size) {
    const float* x  = (const float*)d_in[0];
    const float* wq = (const float*)d_in[1];
    const float* bq = (const float*)d_in[2];
    const float* wk = (const float*)d_in[3];
    const float* bk = (const float*)d_in[4];
    const float* wv = (const float*)d_in[5];
    const float* bv = (const float*)d_in[6];
    const float* wo = (const float*)d_in[7];
    const float* bo = (const float*)d_in[8];
    const float* wg = (const float*)d_in[9];
    const float* bg = (const float*)d_in[10];
    const float* wu = (const float*)d_in[11];
    const float* bu = (const float*)d_in[12];
    const float* wd = (const float*)d_in[13];
    const float* bd = (const float*)d_in[14];
    const float* g1 = (const float*)d_in[15];
    const float* g2 = (const float*)d_in[16];
    float* out = (float*)d_out;

    float *h, *qb_, *kb_, *vb_, *att, *x1, *gate, *hu;
    float *wqT, *wkvT, *woT, *wgT, *wuT, *wdT, *bkv;
    cudaGetSymbolAddress((void**)&h,    g_h);
    cudaGetSymbolAddress((void**)&qb_,  g_q);
    cudaGetSymbolAddress((void**)&kb_,  g_k);
    cudaGetSymbolAddress((void**)&vb_,  g_v);
    cudaGetSymbolAddress((void**)&att,  g_att);
    cudaGetSymbolAddress((void**)&x1,   g_x1);
    cudaGetSymbolAddress((void**)&gate, g_gate);
    cudaGetSymbolAddress((void**)&hu,   g_hu);
    cudaGetSymbolAddress((void**)&wqT,  g_wqT);
    cudaGetSymbolAddress((void**)&wkvT, g_wkvT);
    cudaGetSymbolAddress((void**)&woT,  g_woT);
    cudaGetSymbolAddress((void**)&wgT,  g_wgT);
    cudaGetSymbolAddress((void**)&wuT,  g_wuT);
    cudaGetSymbolAddress((void**)&wdT,  g_wdT);
    cudaGetSymbolAddress((void**)&bkv,  g_bkv);

    cudaFuncSetAttribute(mma_gemm<0>, cudaFuncAttributeMaxDynamicSharedMemorySize, GEMM_SMEM);
    cudaFuncSetAttribute(mma_gemm<1>, cudaFuncAttributeMaxDynamicSharedMemorySize, GEMM_SMEM);
    cudaFuncSetAttribute(mma_gemm<2>, cudaFuncAttributeMaxDynamicSharedMemorySize, GEMM_SMEM);
    cudaFuncSetAttribute(mma_gemm<3>, cudaFuncAttributeMaxDynamicSharedMemorySize, GEMM_SMEM);
    cudaFuncSetAttribute(mma_gemm<4>, cudaFuncAttributeMaxDynamicSharedMemorySize, GEMM_SMEM);
    const int ATTN_SMEM = 3 * 64 * ATP * 4;   // 52224 B
    cudaFuncSetAttribute(attn_kernel, cudaFuncAttributeMaxDynamicSharedMemorySize, ATTN_SMEM);

    dim3 tb(32, 8);
    // 0) weight prep: transpose + tf32 round
    wtrans_kernel<<<dim3(EE/32,  EE/32),  tb>>>(wq, wqT, EE, EE);
    wtrans_kernel<<<dim3(64/32,  EE/32),  tb>>>(wk, wkvT,            EE, 64);
    wtrans_kernel<<<dim3(64/32,  EE/32),  tb>>>(wv, wkvT + 64*EE,    EE, 64);
    wtrans_kernel<<<dim3(EE/32,  EE/32),  tb>>>(wo, woT, EE, EE);
    wtrans_kernel<<<dim3(FFD/32, EE/32),  tb>>>(wg, wgT, EE, FFD);
    wtrans_kernel<<<dim3(FFD/32, EE/32),  tb>>>(wu, wuT, EE, FFD);
    wtrans_kernel<<<dim3(EE/32,  FFD/32), tb>>>(wd, wdT, FFD, EE);
    bkv_kernel<<<1, 128>>>(bk, bv, bkv);

    // 1) rmsnorm(x, g1) -> h (tf32)
    rmsnorm_kernel<<<MM, 256>>>(x, g1, h);
    // 2) projections
    mma_gemm<0><<<dim3(EE/128, MM/128), 256, GEMM_SMEM>>>(h, wqT, bq, nullptr, qb_, EE, EE);
    mma_gemm<4><<<dim3(1,      MM/128), 256, GEMM_SMEM>>>(h, wkvT, bkv, (const float*)vb_, kb_, 128, EE);
    // 3) RoPE
    rope_kernel<<<(MM*HH*32 + 255)/256, 256>>>(qb_, HH, MM*HH*32);
    rope_kernel<<<(MM*32    + 255)/256, 256>>>(kb_, 1,  MM*32);
    // 4) attention (out rounded to tf32 for o-proj)
    attn_kernel<<<dim3(SS/64, BB*HH), 256, ATTN_SMEM>>>(qb_, kb_, vb_, att);
    // 5) o-proj + residual(x)
    mma_gemm<1><<<dim3(EE/128, MM/128), 256, GEMM_SMEM>>>(att, woT, bo, x, x1, EE, EE);
    // 6) rmsnorm(x1, g2) -> h (tf32)
    rmsnorm_kernel<<<MM, 256>>>(x1, g2, h);
    // 7) gate = gelu(h@wg+bg)
    mma_gemm<2><<<dim3(FFD/128, MM/128), 256, GEMM_SMEM>>>(h, wgT, bg, nullptr, gate, FFD, EE);
    // 8) hu = tf32((h@wu+bu) * gate)
    mma_gemm<3><<<dim3(FFD/128, MM/128), 256, GEMM_SMEM>>>(h, wuT, bu, gate, hu, FFD, EE);
    // 9) out = hu@wd + bd + x1
    mma_gemm<1><<<dim3(EE/128, MM/128), 256, GEMM_SMEM>>>(hu, wdT, bd, x1, out, EE, FFD);
}

// round 5
// speedup vs baseline: 3.5239x; 1.3585x over previous
#include <cuda_runtime.h>
#include <stdint.h>
#include <math.h>

#define BB  2
#define SS  2048
#define EE  1024
#define HH  16
#define HD_ 64
#define FFD 4096
#define MM  (BB*SS)   // 4096

// ---------------- scratch (allocation-free) ----------------
static __device__ float g_h   [MM*EE];
static __device__ float g_q   [MM*EE];
static __device__ float g_k   [MM*HD_];
static __device__ float g_v   [MM*HD_];
static __device__ float g_att [MM*EE];
static __device__ float g_x1  [MM*EE];
static __device__ float g_gate[MM*FFD];
static __device__ float g_hu  [MM*FFD];
// transposed (tf32-rounded) weights: WT[N][K]
static __device__ float g_wqT [EE*EE];
static __device__ float g_wkvT[128*EE];
static __device__ float g_woT [EE*EE];
static __device__ float g_wgT [FFD*EE];
static __device__ float g_wuT [FFD*EE];
static __device__ float g_wdT [EE*FFD];
static __device__ float g_bkv [128];

// =================== helpers ===================
__device__ __forceinline__ uint32_t smem_u32(const void* p) {
    uint32_t a;
    asm("{ .reg .u64 t; cvta.to.shared.u64 t, %1; cvt.u32.u64 %0, t; }"
        : "=r"(a) : "l"(p));
    return a;
}
__device__ __forceinline__ float f2tf_f(float f) {
    uint32_t r; asm("cvt.rna.tf32.f32 %0, %1;" : "=r"(r) : "f"(f));
    return __uint_as_float(r);
}
__device__ __forceinline__ uint32_t f2tf_u(float f) {
    uint32_t r; asm("cvt.rna.tf32.f32 %0, %1;" : "=r"(r) : "f"(f));
    return r;
}
__device__ __forceinline__ void cpasync16(uint32_t sp, const void* gp) {
    asm volatile("cp.async.ca.shared.global [%0], [%1], 16;" :: "r"(sp), "l"(gp) : "memory");
}
__device__ __forceinline__ void ldsm4(uint32_t addr, uint32_t& r0, uint32_t& r1,
                                      uint32_t& r2, uint32_t& r3) {
    asm volatile("ldmatrix.sync.aligned.m8n8.x4.shared.b16 {%0,%1,%2,%3}, [%4];"
                 : "=r"(r0), "=r"(r1), "=r"(r2), "=r"(r3) : "r"(addr));
}
__device__ __forceinline__ uint32_t lds_u(uint32_t a) {
    uint32_t v; asm volatile("ld.shared.b32 %0, [%1];" : "=r"(v) : "r"(a)); return v;
}
__device__ __forceinline__ void sts64(uint32_t a, uint32_t v0, uint32_t v1) {
    asm volatile("st.shared.v2.b32 [%0], {%1,%2};" :: "r"(a), "r"(v0), "r"(v1) : "memory");
}
__device__ __forceinline__ void mma_tf32(float* d, const uint32_t* a, const uint32_t* b) {
    asm volatile(
        "mma.sync.aligned.m16n8k8.row.col.f32.tf32.tf32.f32 "
        "{%0,%1,%2,%3}, {%4,%5,%6,%7}, {%8,%9}, {%0,%1,%2,%3};"
        : "+f"(d[0]), "+f"(d[1]), "+f"(d[2]), "+f"(d[3])
        : "r"(a[0]), "r"(a[1]), "r"(a[2]), "r"(a[3]), "r"(b[0]), "r"(b[1]));
}

// smem: A buf = B buf = 128 rows x 36 words = 18432 B each; double buffered
#define BUF_BYTES 18432
#define B_REGION  (2 * BUF_BYTES)
#define GEMM_SMEM (4 * BUF_BYTES)   // 73728

// =================== tf32 mma.sync GEMM (ldmatrix, pre-rounded operands) ===================
// EPI: 0=+bias; 1=+bias+extra; 2=gelu; 3=(+bias)*extra tf32; 4=KV split (tf32)
template<int EPI>
__global__ void __launch_bounds__(256, 2)
mma_gemm(const float* __restrict__ A, const float* __restrict__ WT,
         const float* __restrict__ bias, const float* extra,
         float* __restrict__ C, int N, int K) {
    extern __shared__ char dyn[];
    const uint32_t smem_base = smem_u32(dyn);

    const int tid  = threadIdx.x;
    const int lane = tid & 31;
    const int warp = tid >> 5;
    const int wr = warp & 1;
    const int wc = warp >> 1;
    const int row0 = blockIdx.y * 128, col0 = blockIdx.x * 128;

    const int rp = lane >> 2;
    const int cp = lane & 3;

    const uint32_t a_lm = (uint32_t)(((wr*64 + (lane & 15)) * 36 + ((lane >> 4) & 1) * 4) * 4);
    const uint32_t b_lm = (uint32_t)(((wc*32 + (lane & 7) + ((lane >> 4) & 1) * 8) * 36
                                      + ((lane >> 3) & 1) * 4) * 4);

    float acc[4][4][4];
#pragma unroll
    for (int i = 0; i < 4; i++)
#pragma unroll
        for (int j = 0; j < 4; j++)
#pragma unroll
            for (int q = 0; q < 4; q++) acc[i][j][q] = 0.f;

    auto issue_slab = [&](int buf, int kb) {
        uint32_t as = smem_base + (uint32_t)buf * BUF_BYTES;
        uint32_t bs = smem_base + B_REGION + (uint32_t)buf * BUF_BYTES;
#pragma unroll
        for (int i = 0; i < 4; i++) {
            int f = tid + i * 256;
            int r = f >> 3, c4 = f & 7;
            cpasync16(as + (uint32_t)(r * 144 + c4 * 16),
                      A + (size_t)(row0 + r) * K + kb + c4 * 4);
        }
#pragma unroll
        for (int i = 0; i < 4; i++) {
            int f = tid + i * 256;
            int r = f >> 3, c4 = f & 7;
            cpasync16(bs + (uint32_t)(r * 144 + c4 * 16),
                      WT + (size_t)(col0 + r) * K + kb + c4 * 4);
        }
        asm volatile("cp.async.commit_group;" ::: "memory");
    };

    auto compute = [&](int buf) {
        const uint32_t as = smem_base + (uint32_t)buf * BUF_BYTES + a_lm;
        const uint32_t bs = smem_base + B_REGION + (uint32_t)buf * BUF_BYTES + b_lm;
#pragma unroll
        for (int ks = 0; ks < 4; ks++) {
            uint32_t af[4][4];
#pragma unroll
            for (int mt = 0; mt < 4; mt++)
                ldsm4(as + (uint32_t)(mt * 2304 + ks * 32),
                      af[mt][0], af[mt][1], af[mt][2], af[mt][3]);
            uint32_t bf[4][2];
            ldsm4(bs + (uint32_t)(ks * 32),        bf[0][0], bf[0][1], bf[1][0], bf[1][1]);
            ldsm4(bs + (uint32_t)(2304 + ks * 32), bf[2][0], bf[2][1], bf[3][0], bf[3][1]);
#pragma unroll
            for (int mt = 0; mt < 4; mt++)
#pragma unroll
                for (int nt = 0; nt < 4; nt++)
                    mma_tf32(acc[mt][nt], af[mt], bf[nt]);
        }
    };

    const int nk = K >> 5;
    issue_slab(0, 0);
    for (int kt = 0; kt < nk; kt++) {
        int buf = kt & 1;
        if (kt + 1 < nk) {
            issue_slab(buf ^ 1, (kt + 1) << 5);
            asm volatile("cp.async.wait_group 1;" ::: "memory");
        } else {
            asm volatile("cp.async.wait_group 0;" ::: "memory");
        }
        __syncthreads();
        compute(buf);
        __syncthreads();
    }

#pragma unroll
    for (int mt = 0; mt < 4; mt++) {
#pragma unroll
        for (int nt = 0; nt < 4; nt++) {
            int row = row0 + wr*64 + mt*16 + rp;
            int col = col0 + wc*32 + nt*8 + 2*cp;
#pragma unroll
            for (int half = 0; half < 2; half++) {
                int r = row + half * 8;
                float v0 = acc[mt][nt][half*2 + 0] + bias[col];
                float v1 = acc[mt][nt][half*2 + 1] + bias[col + 1];
                if (EPI == 4) {
                    float2 o = make_float2(f2tf_f(v0), f2tf_f(v1));
                    if (col < 64) *(float2*)&C[(size_t)r * 64 + col] = o;
                    else *(float2*)&((float*)extra)[(size_t)r * 64 + col - 64] = o;
                } else {
                    size_t gi = (size_t)r * N + col;
                    if (EPI == 1) { float2 e = *(const float2*)&extra[gi]; v0 += e.x; v1 += e.y; }
                    else if (EPI == 2) {
                        v0 = 0.5f * v0 * (1.0f + erff(v0 * 0.7071067811865476f));
                        v1 = 0.5f * v1 * (1.0f + erff(v1 * 0.7071067811865476f));
                    } else if (EPI == 3) {
                        float2 e = *(const float2*)&extra[gi];
                        v0 = f2tf_f(v0 * e.x); v1 = f2tf_f(v1 * e.y);
                    }
                    *(float2*)&C[gi] = make_float2(v0, v1);
                }
            }
        }
    }
}

// ---------------- weight transpose + tf32 round ----------------
__global__ void wtrans_kernel(const float* __restrict__ W, float* __restrict__ WT,
                              int K, int N) {
    __shared__ float t[32][33];
    int nb = blockIdx.x * 32, kb = blockIdx.y * 32;
    int tx = threadIdx.x, ty = threadIdx.y;
#pragma unroll
    for (int j = 0; j < 4; j++)
        t[ty + j*8][tx] = W[(size_t)(kb + ty + j*8) * N + nb + tx];
    __syncthreads();
#pragma unroll
    for (int j = 0; j < 4; j++)
        WT[(size_t)(nb + ty + j*8) * K + kb + tx] = f2tf_f(t[tx][ty + j*8]);
}

__global__ void bkv_kernel(const float* __restrict__ bk, const float* __restrict__ bv,
                           float* __restrict__ bkv) {
    int i = threadIdx.x;
    bkv[i] = (i < 64) ? bk[i] : bv[i - 64];
}

// ---------------- rmsnorm (tf32-rounded output) ----------------
__global__ void rmsnorm_kernel(const float* __restrict__ x, const float* __restrict__ g,
                               float* __restrict__ out) {
    int row = blockIdx.x;
    const float* xr = x + (size_t)row * EE;
    float v[4];
    float s = 0.f;
#pragma unroll
    for (int i = 0; i < 4; i++) { v[i] = xr[threadIdx.x + i*256]; s += v[i]*v[i]; }
    __shared__ float red[8];
#pragma unroll
    for (int o = 16; o > 0; o >>= 1) s += __shfl_xor_sync(0xffffffffu, s, o);
    if ((threadIdx.x & 31) == 0) red[threadIdx.x >> 5] = s;
    __syncthreads();
    if (threadIdx.x < 8) {
        float t = red[threadIdx.x];
#pragma unroll
        for (int o = 4; o > 0; o >>= 1) t += __shfl_xor_sync(0xffu, t, o);
        if (threadIdx.x == 0) red[0] = t;
    }
    __syncthreads();
    float ms = red[0] * (1.0f / EE);
    float r  = rsqrtf(ms + 1.1920929e-7f);
#pragma unroll
    for (int i = 0; i < 4; i++) {
        int c = threadIdx.x + i*256;
        out[(size_t)row*EE + c] = f2tf_f(v[i] * r * g[c]);
    }
}

// ---------------- RoPE (in-place, tf32-rounded, optional score scale) ----------------
__global__ void rope_kernel(float* __restrict__ t, int nH, int total, float scale) {
    int idx = blockIdx.x * blockDim.x + threadIdx.x;
    if (idx >= total) return;
    int j    = idx & 31;
    int rest = idx >> 5;
    int h    = rest % nH;
    int row  = rest / nH;
    int s    = row % SS;
    float inv = powf(10000.0f, -(float)j * (1.0f/32.0f));
    float ang = (float)s * inv;
    float c = cosf(ang), sn = sinf(ang);
    size_t base = ((size_t)row * nH + h) * 64;
    float t1 = t[base + j], t2 = t[base + 32 + j];
    t[base + j]      = f2tf_f((t1*c  - t2*sn) * scale);
    t[base + 32 + j] = f2tf_f((t1*sn + t2*c) * scale);
}

// ---------------- Flash attention, tf32 mma.sync (MQA, causal, HD=64) ----------------
// q-tile 64 x key-tile 64, 4 warps (16 q-rows each), double-buffered K/V.
// smem: qs[64][68] @0; per buf {ks[64][68], vs[64][68]} @17408+buf*34816; ps[64][68] @87040
#define ATT_SMEM 104448
__global__ void __launch_bounds__(128)
attn_mma(const float* __restrict__ q, const float* __restrict__ k,
         const float* __restrict__ v, float* __restrict__ out) {
    extern __shared__ char smc[];
    const uint32_t sb = smem_u32(smc);
    const int tid = threadIdx.x, lane = tid & 31, w = tid >> 5;
    const int bh = blockIdx.y, b = bh >> 4, h = bh & 15;
    const int qb = (int)(gridDim.x - 1 - blockIdx.x);   // big tiles first
    const int rp = lane >> 2, cp = lane & 3;

    const uint32_t qs = sb;
    const uint32_t ps = sb + 87040u;

    // ldmatrix bases
    const uint32_t a_lm = (uint32_t)((w*16 + (lane & 15)) * 272 + ((lane >> 4) & 1) * 16);
    const uint32_t b_lm_row = (uint32_t)((lane & 7) + ((lane >> 4) & 1) * 8);
    const uint32_t b_lm_col = (uint32_t)(((lane >> 3) & 1) * 16);

    // load Q tile (group with kv0)
    const float* qg = q + ((size_t)(b*SS + qb*64)) * 1024 + h*64;
#pragma unroll
    for (int i = 0; i < 8; i++) {
        int f = tid + i * 128;
        int r = f >> 4, c4 = f & 15;
        cpasync16(qs + (uint32_t)(r * 272 + c4 * 16), qg + (size_t)r * 1024 + c4 * 4);
    }
    const float* kg = k + (size_t)(b*SS) * 64;
    const float* vg = v + (size_t)(b*SS) * 64;
    auto issue_kv = [&](int buf, int kb) {
        uint32_t ksm = sb + 17408u + (uint32_t)buf * 34816u;
        uint32_t vsm = ksm + 17408u;
#pragma unroll
        for (int i = 0; i < 8; i++) {
            int f = tid + i * 128;
            int r = f >> 4, c4 = f & 15;
            size_t gof = (size_t)(kb*64 + r) * 64 + c4 * 4;
            cpasync16(ksm + (uint32_t)(r * 272 + c4 * 16), kg + gof);
            cpasync16(vsm + (uint32_t)(r * 272 + c4 * 16), vg + gof);
        }
        asm volatile("cp.async.commit_group;" ::: "memory");
    };
    issue_kv(0, 0);

    float o[8][4];
#pragma unroll
    for (int nt = 0; nt < 8; nt++)
#pragma unroll
        for (int j = 0; j < 4; j++) o[nt][j] = 0.f;
    float m0 = -1e30f, m1 = -1e30f, l0 = 0.f, l1 = 0.f;

    for (int kb = 0; kb <= qb; kb++) {
        int buf = kb & 1;
        if (kb < qb) {
            issue_kv(buf ^ 1, kb + 1);
            asm volatile("cp.async.wait_group 1;" ::: "memory");
        } else {
            asm volatile("cp.async.wait_group 0;" ::: "memory");
        }
        __syncthreads();
        const uint32_t ksm = sb + 17408u + (uint32_t)buf * 34816u;
        const uint32_t vsm = ksm + 17408u;

        // ---- S = Q K^T (scale pre-folded into Q) ----
        float s[8][4];
#pragma unroll
        for (int nt = 0; nt < 8; nt++)
#pragma unroll
            for (int j = 0; j < 4; j++) s[nt][j] = 0.f;
#pragma unroll
        for (int ks = 0; ks < 8; ks++) {
            uint32_t af[4];
            ldsm4(qs + a_lm + (uint32_t)(ks * 32), af[0], af[1], af[2], af[3]);
#pragma unroll
            for (int p2 = 0; p2 < 4; p2++) {
                uint32_t bf[4];
                ldsm4(ksm + (uint32_t)((p2*16 + b_lm_row) * 272) + b_lm_col
                          + (uint32_t)(ks * 32),
                      bf[0], bf[1], bf[2], bf[3]);
                mma_tf32(s[p2*2],     af, &bf[0]);
                mma_tf32(s[p2*2 + 1], af, &bf[2]);
            }
        }

        // ---- causal mask on diagonal tile ----
        if (kb == qb) {
#pragma unroll
            for (int nt = 0; nt < 8; nt++) {
                int key0 = nt*8 + 2*cp;
                int r0 = w*16 + rp, r1 = r0 + 8;
                if (key0     > r0) s[nt][0] = -1e30f;
                if (key0 + 1 > r0) s[nt][1] = -1e30f;
                if (key0     > r1) s[nt][2] = -1e30f;
                if (key0 + 1 > r1) s[nt][3] = -1e30f;
            }
        }

        // ---- online softmax (rows rp / rp+8; stats across 4-lane quads) ----
        float mx0 = -1e30f, mx1 = -1e30f;
#pragma unroll
        for (int nt = 0; nt < 8; nt++) {
            mx0 = fmaxf(mx0, fmaxf(s[nt][0], s[nt][1]));
            mx1 = fmaxf(mx1, fmaxf(s[nt][2], s[nt][3]));
        }
        mx0 = fmaxf(mx0, __shfl_xor_sync(0xffffffffu, mx0, 1, 4));
        mx0 = fmaxf(mx0, __shfl_xor_sync(0xffffffffu, mx0, 2, 4));
        mx1 = fmaxf(mx1, __shfl_xor_sync(0xffffffffu, mx1, 1, 4));
        mx1 = fmaxf(mx1, __shfl_xor_sync(0xffffffffu, mx1, 2, 4));
        float mn0 = fmaxf(m0, mx0), mn1 = fmaxf(m1, mx1);
        float al0 = __expf(m0 - mn0), al1 = __expf(m1 - mn1);
        float sum0 = 0.f, sum1 = 0.f;
#pragma unroll
        for (int nt = 0; nt < 8; nt++) {
            s[nt][0] = __expf(s[nt][0] - mn0);
            s[nt][1] = __expf(s[nt][1] - mn0);
            s[nt][2] = __expf(s[nt][2] - mn1);
            s[nt][3] = __expf(s[nt][3] - mn1);
            sum0 += s[nt][0] + s[nt][1];
            sum1 += s[nt][2] + s[nt][3];
        }
        sum0 += __shfl_xor_sync(0xffffffffu, sum0, 1, 4);
        sum0 += __shfl_xor_sync(0xffffffffu, sum0, 2, 4);
        sum1 += __shfl_xor_sync(0xffffffffu, sum1, 1, 4);
        sum1 += __shfl_xor_sync(0xffffffffu, sum1, 2, 4);
        l0 = l0 * al0 + sum0; l1 = l1 * al1 + sum1;
        m0 = mn0; m1 = mn1;
#pragma unroll
        for (int nt = 0; nt < 8; nt++) {
            o[nt][0] *= al0; o[nt][1] *= al0;
            o[nt][2] *= al1; o[nt][3] *= al1;
        }

        // ---- stage P (tf32) to warp-private smem rows ----
        const uint32_t pr0 = ps + (uint32_t)((w*16 + rp) * 272 + 2*cp*4);
        const uint32_t pr1 = pr0 + 8u * 272u;
#pragma unroll
        for (int nt = 0; nt < 8; nt++) {
            sts64(pr0 + (uint32_t)(nt * 32), f2tf_u(s[nt][0]), f2tf_u(s[nt][1]));
            sts64(pr1 + (uint32_t)(nt * 32), f2tf_u(s[nt][2]), f2tf_u(s[nt][3]));
        }
        __syncwarp();

        // ---- O += P V ----
        const uint32_t pa0 = ps + (uint32_t)((w*16 + rp) * 272 + cp*4);
#pragma unroll
        for (int ks = 0; ks < 8; ks++) {
            uint32_t pa[4];
            uint32_t pb_ = pa0 + (uint32_t)(ks * 32);
            pa[0] = lds_u(pb_);
            pa[1] = lds_u(pb_ + 8u*272u);
            pa[2] = lds_u(pb_ + 16u);
            pa[3] = lds_u(pb_ + 8u*272u + 16u);
            const uint32_t vb0 = vsm + (uint32_t)((ks*8 + cp) * 272 + rp*4);
#pragma unroll
            for (int nt = 0; nt < 8; nt++) {
                uint32_t bv[2];
                bv[0] = lds_u(vb0 + (uint32_t)(nt * 32));
                bv[1] = lds_u(vb0 + (uint32_t)(nt * 32) + 4u*272u);
                mma_tf32(o[nt], pa, bv);
            }
        }
        __syncthreads();
    }

    // ---- write out (tf32-rounded for o-proj) ----
    float inv0 = 1.0f / l0, inv1 = 1.0f / l1;
    const int r0 = b*SS + qb*64 + w*16 + rp;
#pragma unroll
    for (int nt = 0; nt < 8; nt++) {
        int d = h*64 + nt*8 + 2*cp;
        *(float2*)&out[(size_t)r0 * 1024 + d] =
            make_float2(f2tf_f(o[nt][0] * inv0), f2tf_f(o[nt][1] * inv0));
        *(float2*)&out[(size_t)(r0 + 8) * 1024 + d] =
            make_float2(f2tf_f(o[nt][2] * inv1), f2tf_f(o[nt][3] * inv1));
    }
}

// ---------------- launch ----------------
extern "C" void kernel_launch(void* const* d_in, const int* in_sizes, int n_in,
                              void* d_out, int out_size) {
    const float* x  = (const float*)d_in[0];
    const float* wq = (const float*)d_in[1];
    const float* bq = (const float*)d_in[2];
    const float* wk = (const float*)d_in[3];
    const float* bk = (const float*)d_in[4];
    const float* wv = (const float*)d_in[5];
    const float* bv = (const float*)d_in[6];
    const float* wo = (const float*)d_in[7];
    const float* bo = (const float*)d_in[8];
    const float* wg = (const float*)d_in[9];
    const float* bg = (const float*)d_in[10];
    const float* wu = (const float*)d_in[11];
    const float* bu = (const float*)d_in[12];
    const float* wd = (const float*)d_in[13];
    const float* bd = (const float*)d_in[14];
    const float* g1 = (const float*)d_in[15];
    const float* g2 = (const float*)d_in[16];
    float* out = (float*)d_out;

    float *h, *qb_, *kb_, *vb_, *att, *x1, *gate, *hu;
    float *wqT, *wkvT, *woT, *wgT, *wuT, *wdT, *bkv;
    cudaGetSymbolAddress((void**)&h,    g_h);
    cudaGetSymbolAddress((void**)&qb_,  g_q);
    cudaGetSymbolAddress((void**)&kb_,  g_k);
    cudaGetSymbolAddress((void**)&vb_,  g_v);
    cudaGetSymbolAddress((void**)&att,  g_att);
    cudaGetSymbolAddress((void**)&x1,   g_x1);
    cudaGetSymbolAddress((void**)&gate, g_gate);
    cudaGetSymbolAddress((void**)&hu,   g_hu);
    cudaGetSymbolAddress((void**)&wqT,  g_wqT);
    cudaGetSymbolAddress((void**)&wkvT, g_wkvT);
    cudaGetSymbolAddress((void**)&woT,  g_woT);
    cudaGetSymbolAddress((void**)&wgT,  g_wgT);
    cudaGetSymbolAddress((void**)&wuT,  g_wuT);
    cudaGetSymbolAddress((void**)&wdT,  g_wdT);
    cudaGetSymbolAddress((void**)&bkv,  g_bkv);

    cudaFuncSetAttribute(mma_gemm<0>, cudaFuncAttributeMaxDynamicSharedMemorySize, GEMM_SMEM);
    cudaFuncSetAttribute(mma_gemm<1>, cudaFuncAttributeMaxDynamicSharedMemorySize, GEMM_SMEM);
    cudaFuncSetAttribute(mma_gemm<2>, cudaFuncAttributeMaxDynamicSharedMemorySize, GEMM_SMEM);
    cudaFuncSetAttribute(mma_gemm<3>, cudaFuncAttributeMaxDynamicSharedMemorySize, GEMM_SMEM);
    cudaFuncSetAttribute(mma_gemm<4>, cudaFuncAttributeMaxDynamicSharedMemorySize, GEMM_SMEM);
    cudaFuncSetAttribute(attn_mma,    cudaFuncAttributeMaxDynamicSharedMemorySize, ATT_SMEM);

    dim3 tb(32, 8);
    wtrans_kernel<<<dim3(EE/32,  EE/32),  tb>>>(wq, wqT, EE, EE);
    wtrans_kernel<<<dim3(64/32,  EE/32),  tb>>>(wk, wkvT,         EE, 64);
    wtrans_kernel<<<dim3(64/32,  EE/32),  tb>>>(wv, wkvT + 64*EE, EE, 64);
    wtrans_kernel<<<dim3(EE/32,  EE/32),  tb>>>(wo, woT, EE, EE);
    wtrans_kernel<<<dim3(FFD/32, EE/32),  tb>>>(wg, wgT, EE, FFD);
    wtrans_kernel<<<dim3(FFD/32, EE/32),  tb>>>(wu, wuT, EE, FFD);
    wtrans_kernel<<<dim3(EE/32,  FFD/32), tb>>>(wd, wdT, FFD, EE);
    bkv_kernel<<<1, 128>>>(bk, bv, bkv);

    // 1) rmsnorm(x, g1) -> h (tf32)
    rmsnorm_kernel<<<MM, 256>>>(x, g1, h);
    // 2) projections
    mma_gemm<0><<<dim3(EE/128, MM/128), 256, GEMM_SMEM>>>(h, wqT, bq, nullptr, qb_, EE, EE);
    mma_gemm<4><<<dim3(1,      MM/128), 256, GEMM_SMEM>>>(h, wkvT, bkv, (const float*)vb_, kb_, 128, EE);
    // 3) RoPE (q gets 1/sqrt(HD)=0.125 folded in; both tf32-rounded)
    rope_kernel<<<(MM*HH*32 + 255)/256, 256>>>(qb_, HH, MM*HH*32, 0.125f);
    rope_kernel<<<(MM*32    + 255)/256, 256>>>(kb_, 1,  MM*32,    1.0f);
    // 4) attention (tensor cores)
    attn_mma<<<dim3(SS/64, BB*HH), 128, ATT_SMEM>>>(qb_, kb_, vb_, att);
    // 5) o-proj + residual(x)
    mma_gemm<1><<<dim3(EE/128, MM/128), 256, GEMM_SMEM>>>(att, woT, bo, x, x1, EE, EE);
    // 6) rmsnorm(x1, g2) -> h (tf32)
    rmsnorm_kernel<<<MM, 256>>>(x1, g2, h);
    // 7) gate = gelu(h@wg+bg)
    mma_gemm<2><<<dim3(FFD/128, MM/128), 256, GEMM_SMEM>>>(h, wgT, bg, nullptr, gate, FFD, EE);
    // 8) hu = tf32((h@wu+bu) * gate)
    mma_gemm<3><<<dim3(FFD/128, MM/128), 256, GEMM_SMEM>>>(h, wuT, bu, gate, hu, FFD, EE);
    // 9) out = hu@wd + bd + x1
    mma_gemm<1><<<dim3(EE/128, MM/128), 256, GEMM_SMEM>>>(hu, wdT, bd, x1, out, EE, FFD);
}